// round 5
// baseline (speedup 1.0000x reference)
#include <cuda_runtime.h>
#include <math.h>
#include <stdint.h>

// Problem constants
#define D     1024
#define H_    16
#define HD    64
#define FF    4096
#define NB    2
#define LQ    2048
#define MROWS (NB * LQ)   // 4096
#define EPS   1e-5f

// ---------------------------------------------------------------------------
// Scratch (device globals — no allocation allowed)
// ---------------------------------------------------------------------------
__device__ float g_qkv  [MROWS * 3 * D];
__device__ float g_attn [MROWS * D];
__device__ float g_proj [MROWS * D];
__device__ float g_h    [MROWS * D];
__device__ float g_ff1  [MROWS * FF];
__device__ float g_ff2  [MROWS * D];
__device__ float g_wqkvT[3 * D * D];
__device__ float g_woT  [D * D];
__device__ float g_w1T  [FF * D];
__device__ float g_w2T  [D * FF];

__device__ __forceinline__ float* scratch(int id) {
    switch (id) {
        case 0:  return g_qkv;
        case 1:  return g_attn;
        case 2:  return g_proj;
        case 3:  return g_h;
        case 4:  return g_ff1;
        case 5:  return g_ff2;
        case 6:  return g_wqkvT;
        case 7:  return g_woT;
        case 8:  return g_w1T;
        default: return g_w2T;
    }
}

// ---------------------------------------------------------------------------
// tf32 helpers (mma.sync path — base sm_103 target OK)
// ---------------------------------------------------------------------------
__device__ __forceinline__ uint32_t f2tf32(float x) {
    uint32_t r;
    asm("cvt.rna.tf32.f32 %0, %1;" : "=r"(r) : "f"(x));
    return r;
}

__device__ __forceinline__ uint32_t w2tf32(uint32_t w) {
    uint32_t r;
    asm("cvt.rna.tf32.f32 %0, %1;" : "=r"(r) : "f"(__uint_as_float(w)));
    return r;
}

__device__ __forceinline__ void mma_tf32(float* c, const uint32_t* a, const uint32_t* b) {
    asm volatile(
        "mma.sync.aligned.m16n8k8.row.col.f32.tf32.tf32.f32 "
        "{%0,%1,%2,%3}, {%4,%5,%6,%7}, {%8,%9}, {%0,%1,%2,%3};"
        : "+f"(c[0]), "+f"(c[1]), "+f"(c[2]), "+f"(c[3])
        : "r"(a[0]), "r"(a[1]), "r"(a[2]), "r"(a[3]),
          "r"(b[0]), "r"(b[1]));
}

__device__ __forceinline__ void cp_async16(uint32_t smem_u32, const void* gptr) {
    asm volatile("cp.async.cg.shared.global [%0], [%1], 16;"
                 :: "r"(smem_u32), "l"(gptr));
}
__device__ __forceinline__ void cp_commit() {
    asm volatile("cp.async.commit_group;" ::: "memory");
}
__device__ __forceinline__ void cp_wait1() {
    asm volatile("cp.async.wait_group 1;" ::: "memory");
}
__device__ __forceinline__ void cp_wait0() {
    asm volatile("cp.async.wait_group 0;" ::: "memory");
}

// ---------------------------------------------------------------------------
// Weight transpose: dst[c][r] = tf32_rna(src[r][c])  (dst feeds GEMM B only)
// ---------------------------------------------------------------------------
__global__ __launch_bounds__(256)
void transpose_k(const float* __restrict__ src, int dstId, int R, int C)
{
    __shared__ float t[32][33];
    float* dst = scratch(dstId);
    const int bx = blockIdx.x * 32;
    const int by = blockIdx.y * 32;
    const int tx = threadIdx.x & 31;
    const int ty = threadIdx.x >> 5;
    #pragma unroll
    for (int i = 0; i < 32; i += 8)
        t[ty + i][tx] = src[(size_t)(by + ty + i) * C + bx + tx];
    __syncthreads();
    #pragma unroll
    for (int i = 0; i < 32; i += 8)
        dst[(size_t)(bx + ty + i) * R + by + tx] =
            __uint_as_float(f2tf32(t[tx][ty + i]));
}

// ---------------------------------------------------------------------------
// TF32 tensor-core GEMM, cp.async 3-stage pipeline.
// C[M,N] = A[M,K] @ Bt[N,K]^T + bias (opt ReLU). Tile 128x128, BK=16.
// Smem row layout (20-word stride): 16B slots [k0-3][k8-11][k4-7][k12-15]
// -> cp.async lands contiguous 16B; frag loads are conflict-free lds.32.
// B pre-rounded to tf32 (transpose_k); A converted at frag load (cvt.rna).
// ---------------------------------------------------------------------------
#define RS 20           // words per smem row
#define STG_W (128 * RS) // words per stage (2560)

__global__ __launch_bounds__(256)
void gemm_tf32(const float* __restrict__ Aext, int Aid, int Bid,
               const float* __restrict__ bias,
               float* __restrict__ Cext, int Cid,
               int M, int N, int K, int relu)
{
    extern __shared__ uint32_t dynsm[];
    uint32_t* As = dynsm;               // 3 stages
    uint32_t* Bs = dynsm + 3 * STG_W;   // 3 stages

    const float* A  = Aext ? Aext : scratch(Aid);
    const float* Bt = scratch(Bid);
    float*       C  = Cext ? Cext : scratch(Cid);

    const int tid   = threadIdx.x;
    const int wid   = tid >> 5;
    const int lane  = tid & 31;
    const int gid   = lane >> 2;
    const int tig   = lane & 3;
    const int warpM = (wid & 1) * 64;
    const int warpN = (wid >> 1) * 32;
    const int m0    = blockIdx.y * 128;
    const int n0    = blockIdx.x * 128;

    // loader coords
    const int lr   = tid >> 2;                         // 0..63
    const int lc4  = tid & 3;                          // source 16B group
    const int slot = ((lc4 & 1) << 1) | (lc4 >> 1);    // dest slot
    const float* a_src0 = &A [(size_t)(m0 + lr)      * K + lc4 * 4];
    const float* a_src1 = &A [(size_t)(m0 + lr + 64) * K + lc4 * 4];
    const float* b_src0 = &Bt[(size_t)(n0 + lr)      * K + lc4 * 4];
    const float* b_src1 = &Bt[(size_t)(n0 + lr + 64) * K + lc4 * 4];
    const uint32_t a_dst0 = (uint32_t)__cvta_generic_to_shared(&As[0]) + (lr * RS + slot * 4) * 4;
    const uint32_t a_dst1 = a_dst0 + 64 * RS * 4;
    const uint32_t b_dst0 = (uint32_t)__cvta_generic_to_shared(&Bs[0]) + (lr * RS + slot * 4) * 4;
    const uint32_t b_dst1 = b_dst0 + 64 * RS * 4;

    float acc[4][4][4];
    #pragma unroll
    for (int mt = 0; mt < 4; mt++)
        #pragma unroll
        for (int nt = 0; nt < 4; nt++)
            #pragma unroll
            for (int c = 0; c < 4; c++) acc[mt][nt][c] = 0.f;

    const int nk = K >> 4;

    // prolog: stages 0,1
    #pragma unroll
    for (int s = 0; s < 2; s++) {
        const uint32_t so = (uint32_t)(s * STG_W * 4);
        const int ko = s * 16;
        cp_async16(a_dst0 + so, a_src0 + ko);
        cp_async16(a_dst1 + so, a_src1 + ko);
        cp_async16(b_dst0 + so, b_src0 + ko);
        cp_async16(b_dst1 + so, b_src1 + ko);
        cp_commit();
    }

    int buf = 0;
    for (int kc = 0; kc < nk; kc++) {
        if (kc + 2 < nk) cp_wait1(); else cp_wait0();
        __syncthreads();

        // issue stage kc+2 (overwrites buf read 3 iterations ago — safe)
        if (kc + 2 < nk) {
            const int nbuf = (buf + 2 > 2) ? buf - 1 : buf + 2;
            const uint32_t so = (uint32_t)(nbuf * STG_W * 4);
            const int ko = (kc + 2) * 16;
            cp_async16(a_dst0 + so, a_src0 + ko);
            cp_async16(a_dst1 + so, a_src1 + ko);
            cp_async16(b_dst0 + so, b_src0 + ko);
            cp_async16(b_dst1 + so, b_src1 + ko);
            cp_commit();
        }

        const uint32_t* as = As + buf * STG_W;
        const uint32_t* bs = Bs + buf * STG_W;

        #pragma unroll
        for (int ks = 0; ks < 2; ks++) {
            uint32_t bfr[4][2];
            #pragma unroll
            for (int nt = 0; nt < 4; nt++) {
                const uint32_t* bp = &bs[(warpN + nt * 8 + gid) * RS + ks * 4 + tig];
                bfr[nt][0] = bp[0];
                bfr[nt][1] = bp[8];
            }
            #pragma unroll
            for (int mt = 0; mt < 4; mt++) {
                const uint32_t* plo = &as[(warpM + mt * 16 + gid) * RS + ks * 4 + tig];
                const uint32_t* phi = plo + 8 * RS;
                uint32_t af[4];
                af[0] = w2tf32(plo[0]);
                af[1] = w2tf32(phi[0]);
                af[2] = w2tf32(plo[8]);
                af[3] = w2tf32(phi[8]);
                #pragma unroll
                for (int nt = 0; nt < 4; nt++)
                    mma_tf32(acc[mt][nt], af, bfr[nt]);
            }
        }
        buf = (buf == 2) ? 0 : buf + 1;
    }

    #pragma unroll
    for (int nt = 0; nt < 4; nt++) {
        const int n = n0 + warpN + nt * 8 + 2 * tig;
        const float b0 = bias[n], b1 = bias[n + 1];
        #pragma unroll
        for (int mt = 0; mt < 4; mt++) {
            const int m = m0 + warpM + mt * 16 + gid;
            float2 v0 = make_float2(acc[mt][nt][0] + b0, acc[mt][nt][1] + b1);
            float2 v1 = make_float2(acc[mt][nt][2] + b0, acc[mt][nt][3] + b1);
            if (relu) {
                v0.x = fmaxf(v0.x, 0.f); v0.y = fmaxf(v0.y, 0.f);
                v1.x = fmaxf(v1.x, 0.f); v1.y = fmaxf(v1.y, 0.f);
            }
            *(float2*)&C[(size_t)m * N + n]       = v0;
            *(float2*)&C[(size_t)(m + 8) * N + n] = v1;
        }
    }
}

#define GEMM_SMEM (6 * STG_W * 4)   // 61440 bytes

// ---------------------------------------------------------------------------
// Tensor-core flash attention (tf32 mma.sync) — unchanged from R4
// ---------------------------------------------------------------------------
#define KS_STRIDE 72
#define VS_STRIDE 74

__global__ __launch_bounds__(128)
void attn_mma()
{
    __shared__ uint32_t sm[64 * KS_STRIDE + 64 * VS_STRIDE];

    const int nB  = blockIdx.z;
    const int h   = blockIdx.y;
    const int q0  = blockIdx.x * 128;
    const int tid = threadIdx.x;
    const int wid = tid >> 5;
    const int lane = tid & 31;
    const int gid  = lane >> 2;
    const int tig  = lane & 3;
    const int warpM = wid * 32;
    const float qscale = 0.125f * 1.44269504f;

    #pragma unroll
    for (int t = 0; t < 16; t++) {
        const int i  = tid + t * 128;
        const int r  = i >> 4;
        const int c4 = i & 15;
        const float4 v = *(const float4*)&g_qkv[(size_t)(nB * LQ + q0 + r) * (3 * D) + h * HD + c4 * 4];
        uint32_t* dst = &sm[r * KS_STRIDE + (c4 >> 2) * 16 + ((c4 & 3) >> 1) * 8 + (c4 & 1)];
        dst[0] = f2tf32(v.x * qscale); dst[2] = f2tf32(v.y * qscale);
        dst[4] = f2tf32(v.z * qscale); dst[6] = f2tf32(v.w * qscale);
    }
    __syncthreads();

    uint32_t qf[2][8][4];
    #pragma unroll
    for (int mt = 0; mt < 2; mt++) {
        const int rlo = warpM + mt * 16 + gid;
        #pragma unroll
        for (int ks = 0; ks < 8; ks++) {
            uint2 lo = *(const uint2*)&sm[ rlo      * KS_STRIDE + (ks >> 1) * 16 + (ks & 1) * 8 + 2 * tig];
            uint2 hi = *(const uint2*)&sm[(rlo + 8) * KS_STRIDE + (ks >> 1) * 16 + (ks & 1) * 8 + 2 * tig];
            qf[mt][ks][0] = lo.x; qf[mt][ks][1] = hi.x;
            qf[mt][ks][2] = lo.y; qf[mt][ks][3] = hi.y;
        }
    }
    __syncthreads();

    uint32_t* Ks = sm;
    uint32_t* Vs = sm + 64 * KS_STRIDE;

    float oac[2][8][4];
    #pragma unroll
    for (int mt = 0; mt < 2; mt++)
        #pragma unroll
        for (int nt = 0; nt < 8; nt++)
            #pragma unroll
            for (int c = 0; c < 4; c++) oac[mt][nt][c] = 0.f;
    float mrow[2][2] = {{-1e30f, -1e30f}, {-1e30f, -1e30f}};
    float lrow[2][2] = {{0.f, 0.f}, {0.f, 0.f}};

    for (int kt = 0; kt < LQ / 64; kt++) {
        #pragma unroll
        for (int t = 0; t < 8; t++) {
            const int i  = tid + t * 128;
            const int r  = i >> 4;
            const int c4 = i & 15;
            const size_t base = (size_t)(nB * LQ + kt * 64 + r) * (3 * D) + h * HD + c4 * 4;
            const float4 v = *(const float4*)&g_qkv[base + D];
            uint32_t* dst = &Ks[r * KS_STRIDE + (c4 >> 2) * 16 + ((c4 & 3) >> 1) * 8 + (c4 & 1)];
            dst[0] = f2tf32(v.x); dst[2] = f2tf32(v.y);
            dst[4] = f2tf32(v.z); dst[6] = f2tf32(v.w);
        }
        #pragma unroll
        for (int t = 0; t < 8; t++) {
            const int i   = tid + t * 128;
            const int key = i >> 4;
            const int c4  = i & 15;
            const size_t base = (size_t)(nB * LQ + kt * 64 + key) * (3 * D) + h * HD + c4 * 4;
            const float4 v = *(const float4*)&g_qkv[base + 2 * D];
            const int kpos = (key >> 4) * 16 + ((key & 3) << 1) + ((key >> 2) & 1) + (key & 8);
            const int d0 = c4 * 4;
            Vs[(d0 + 0) * VS_STRIDE + kpos] = f2tf32(v.x);
            Vs[(d0 + 1) * VS_STRIDE + kpos] = f2tf32(v.y);
            Vs[(d0 + 2) * VS_STRIDE + kpos] = f2tf32(v.z);
            Vs[(d0 + 3) * VS_STRIDE + kpos] = f2tf32(v.w);
        }
        __syncthreads();

        float sacc[2][8][4];
        #pragma unroll
        for (int mt = 0; mt < 2; mt++)
            #pragma unroll
            for (int nt = 0; nt < 8; nt++)
                #pragma unroll
                for (int c = 0; c < 4; c++) sacc[mt][nt][c] = 0.f;

        #pragma unroll
        for (int ks = 0; ks < 8; ks++) {
            #pragma unroll
            for (int nt = 0; nt < 8; nt++) {
                uint2 bv = *(const uint2*)&Ks[(nt * 8 + gid) * KS_STRIDE + (ks >> 1) * 16 + (ks & 1) * 8 + 2 * tig];
                uint32_t bf[2] = {bv.x, bv.y};
                mma_tf32(sacc[0][nt], qf[0][ks], bf);
                mma_tf32(sacc[1][nt], qf[1][ks], bf);
            }
        }

        #pragma unroll
        for (int mt = 0; mt < 2; mt++) {
            float mx0 = -1e30f, mx1 = -1e30f;
            #pragma unroll
            for (int nt = 0; nt < 8; nt++) {
                mx0 = fmaxf(mx0, fmaxf(sacc[mt][nt][0], sacc[mt][nt][1]));
                mx1 = fmaxf(mx1, fmaxf(sacc[mt][nt][2], sacc[mt][nt][3]));
            }
            mx0 = fmaxf(mx0, __shfl_xor_sync(0xFFFFFFFFu, mx0, 1));
            mx0 = fmaxf(mx0, __shfl_xor_sync(0xFFFFFFFFu, mx0, 2));
            mx1 = fmaxf(mx1, __shfl_xor_sync(0xFFFFFFFFu, mx1, 1));
            mx1 = fmaxf(mx1, __shfl_xor_sync(0xFFFFFFFFu, mx1, 2));

            const float mn0 = fmaxf(mrow[mt][0], mx0);
            const float mn1 = fmaxf(mrow[mt][1], mx1);
            const float cr0 = exp2f(mrow[mt][0] - mn0);
            const float cr1 = exp2f(mrow[mt][1] - mn1);
            mrow[mt][0] = mn0;
            mrow[mt][1] = mn1;

            float ls0 = 0.f, ls1 = 0.f;
            #pragma unroll
            for (int nt = 0; nt < 8; nt++) {
                sacc[mt][nt][0] = exp2f(sacc[mt][nt][0] - mn0);
                sacc[mt][nt][1] = exp2f(sacc[mt][nt][1] - mn0);
                sacc[mt][nt][2] = exp2f(sacc[mt][nt][2] - mn1);
                sacc[mt][nt][3] = exp2f(sacc[mt][nt][3] - mn1);
                ls0 += sacc[mt][nt][0] + sacc[mt][nt][1];
                ls1 += sacc[mt][nt][2] + sacc[mt][nt][3];
            }
            ls0 += __shfl_xor_sync(0xFFFFFFFFu, ls0, 1);
            ls0 += __shfl_xor_sync(0xFFFFFFFFu, ls0, 2);
            ls1 += __shfl_xor_sync(0xFFFFFFFFu, ls1, 1);
            ls1 += __shfl_xor_sync(0xFFFFFFFFu, ls1, 2);
            lrow[mt][0] = lrow[mt][0] * cr0 + ls0;
            lrow[mt][1] = lrow[mt][1] * cr1 + ls1;

            #pragma unroll
            for (int nt = 0; nt < 8; nt++) {
                oac[mt][nt][0] *= cr0; oac[mt][nt][1] *= cr0;
                oac[mt][nt][2] *= cr1; oac[mt][nt][3] *= cr1;
            }
        }

        const int s1 = (lane & ~3) | (tig >> 1);
        const int s2 = s1 + 2;
        const bool odd = (tig & 1) != 0;
        #pragma unroll
        for (int kk = 0; kk < 8; kk++) {
            uint32_t pa[2][4];
            #pragma unroll
            for (int mt = 0; mt < 2; mt++) {
                const float c0 = sacc[mt][kk][0], c1 = sacc[mt][kk][1];
                const float c2 = sacc[mt][kk][2], c3 = sacc[mt][kk][3];
                const float x0 = __shfl_sync(0xFFFFFFFFu, c0, s1);
                const float x1 = __shfl_sync(0xFFFFFFFFu, c1, s1);
                const float x2 = __shfl_sync(0xFFFFFFFFu, c2, s1);
                const float x3 = __shfl_sync(0xFFFFFFFFu, c3, s1);
                const float y0 = __shfl_sync(0xFFFFFFFFu, c0, s2);
                const float y1 = __shfl_sync(0xFFFFFFFFu, c1, s2);
                const float y2 = __shfl_sync(0xFFFFFFFFu, c2, s2);
                const float y3 = __shfl_sync(0xFFFFFFFFu, c3, s2);
                pa[mt][0] = f2tf32(odd ? x1 : x0);
                pa[mt][1] = f2tf32(odd ? x3 : x2);
                pa[mt][2] = f2tf32(odd ? y1 : y0);
                pa[mt][3] = f2tf32(odd ? y3 : y2);
            }
            #pragma unroll
            for (int ntd = 0; ntd < 8; ntd++) {
                uint2 bv = *(const uint2*)&Vs[(ntd * 8 + gid) * VS_STRIDE + (kk >> 1) * 16 + (kk & 1) * 8 + 2 * tig];
                uint32_t bf[2] = {bv.x, bv.y};
                mma_tf32(oac[0][ntd], pa[0], bf);
                mma_tf32(oac[1][ntd], pa[1], bf);
            }
        }
        __syncthreads();
    }

    #pragma unroll
    for (int mt = 0; mt < 2; mt++) {
        const float inv0 = 1.f / lrow[mt][0];
        const float inv1 = 1.f / lrow[mt][1];
        const int grow = nB * LQ + q0 + warpM + mt * 16 + gid;
        #pragma unroll
        for (int ntd = 0; ntd < 8; ntd++) {
            const int col = h * HD + ntd * 8 + 2 * tig;
            *(float2*)&g_attn[(size_t)grow * D + col] =
                make_float2(oac[mt][ntd][0] * inv0, oac[mt][ntd][1] * inv0);
            *(float2*)&g_attn[(size_t)(grow + 8) * D + col] =
                make_float2(oac[mt][ntd][2] * inv1, oac[mt][ntd][3] * inv1);
        }
    }
}

// ---------------------------------------------------------------------------
// Residual add + LayerNorm
// ---------------------------------------------------------------------------
__global__ __launch_bounds__(256)
void add_ln_kernel(const float* __restrict__ aext, int aid,
                   const float* __restrict__ bext, int bid,
                   const float* __restrict__ gamma,
                   const float* __restrict__ beta,
                   float* __restrict__ outext, int outid)
{
    const float* a = aext ? aext : scratch(aid);
    const float* b = bext ? bext : scratch(bid);
    float*       o = outext ? outext : scratch(outid);

    const int row = blockIdx.x;
    const int tid = threadIdx.x;
    const size_t base = (size_t)row * D;

    float v[4];
    float s = 0.f, s2 = 0.f;
    #pragma unroll
    for (int i = 0; i < 4; i++) {
        int col = tid + i * 256;
        float x = a[base + col] + b[base + col];
        v[i] = x;
        s  += x;
        s2 += x * x;
    }
    #pragma unroll
    for (int off = 16; off; off >>= 1) {
        s  += __shfl_xor_sync(0xFFFFFFFFu, s,  off);
        s2 += __shfl_xor_sync(0xFFFFFFFFu, s2, off);
    }
    __shared__ float rs[8], rs2[8];
    const int warp = tid >> 5, lane = tid & 31;
    if (lane == 0) { rs[warp] = s; rs2[warp] = s2; }
    __syncthreads();
    float ts = 0.f, ts2 = 0.f;
    #pragma unroll
    for (int w = 0; w < 8; w++) { ts += rs[w]; ts2 += rs2[w]; }

    const float mu  = ts * (1.f / D);
    const float var = ts2 * (1.f / D) - mu * mu;
    const float inv = rsqrtf(var + EPS);

    #pragma unroll
    for (int i = 0; i < 4; i++) {
        int col = tid + i * 256;
        o[base + col] = (v[i] - mu) * inv * gamma[col] + beta[col];
    }
}

// ---------------------------------------------------------------------------
// Launch
// ---------------------------------------------------------------------------
extern "C" void kernel_launch(void* const* d_in, const int* in_sizes, int n_in,
                              void* d_out, int out_size)
{
    const float* x     = (const float*)d_in[0];
    const float* w_qkv = (const float*)d_in[1];
    const float* b_qkv = (const float*)d_in[2];
    const float* w_o   = (const float*)d_in[3];
    const float* b_o   = (const float*)d_in[4];
    const float* g1    = (const float*)d_in[5];
    const float* be1   = (const float*)d_in[6];
    const float* w1    = (const float*)d_in[7];
    const float* b1    = (const float*)d_in[8];
    const float* w2    = (const float*)d_in[9];
    const float* b2    = (const float*)d_in[10];
    const float* g2    = (const float*)d_in[11];
    const float* be2   = (const float*)d_in[12];
    float* out = (float*)d_out;

    cudaFuncSetAttribute(gemm_tf32,
                         cudaFuncAttributeMaxDynamicSharedMemorySize, GEMM_SMEM);

    // Transpose weights -> [N,K] K-major tf32-rounded operands
    transpose_k<<<dim3(3 * D / 32, D / 32), 256>>>(w_qkv, 6, D, 3 * D);
    transpose_k<<<dim3(D / 32,     D / 32), 256>>>(w_o,   7, D, D);
    transpose_k<<<dim3(FF / 32,    D / 32), 256>>>(w1,    8, D, FF);
    transpose_k<<<dim3(D / 32,    FF / 32), 256>>>(w2,    9, FF, D);

    // 1. QKV
    gemm_tf32<<<dim3(3 * D / 128, MROWS / 128), 256, GEMM_SMEM>>>(
        x, -1, 6, b_qkv, nullptr, 0, MROWS, 3 * D, D, 0);

    // 2. attention (tensor-core flash)
    attn_mma<<<dim3(LQ / 128, H_, NB), 128>>>();

    // 3. proj
    gemm_tf32<<<dim3(D / 128, MROWS / 128), 256, GEMM_SMEM>>>(
        nullptr, 1, 7, b_o, nullptr, 2, MROWS, D, D, 0);

    // 4. h = LN(proj + x)
    add_ln_kernel<<<MROWS, 256>>>(nullptr, 2, x, -1, g1, be1, nullptr, 3);

    // 5. FF1 (+ReLU)
    gemm_tf32<<<dim3(FF / 128, MROWS / 128), 256, GEMM_SMEM>>>(
        nullptr, 3, 8, b1, nullptr, 4, MROWS, FF, D, 1);

    // 6. FF2
    gemm_tf32<<<dim3(D / 128, MROWS / 128), 256, GEMM_SMEM>>>(
        nullptr, 4, 9, b2, nullptr, 5, MROWS, D, FF, 0);

    // 7. out = LN(h + ff2)
    add_ln_kernel<<<MROWS, 256>>>(nullptr, 3, nullptr, 5, g2, be2, out, -1);
}

// round 6
// speedup vs baseline: 1.1742x; 1.1742x over previous
#include <cuda_runtime.h>
#include <math.h>
#include <stdint.h>

// Problem constants
#define D     1024
#define H_    16
#define HD    64
#define FF    4096
#define NB    2
#define LQ    2048
#define MROWS (NB * LQ)   // 4096
#define EPS   1e-5f

// ---------------------------------------------------------------------------
// Scratch (device globals — no allocation allowed)
// ---------------------------------------------------------------------------
__device__ float g_qkv  [MROWS * 3 * D];
__device__ float g_attn [MROWS * D];
__device__ float g_proj [MROWS * D];
__device__ float g_h    [MROWS * D];
__device__ float g_ff1  [MROWS * FF];
__device__ float g_ff2  [MROWS * D];
__device__ float g_wqkvT[3 * D * D];
__device__ float g_woT  [D * D];
__device__ float g_w1T  [FF * D];
__device__ float g_w2T  [D * FF];

__device__ __forceinline__ float* scratch(int id) {
    switch (id) {
        case 0:  return g_qkv;
        case 1:  return g_attn;
        case 2:  return g_proj;
        case 3:  return g_h;
        case 4:  return g_ff1;
        case 5:  return g_ff2;
        case 6:  return g_wqkvT;
        case 7:  return g_woT;
        case 8:  return g_w1T;
        default: return g_w2T;
    }
}

// ---------------------------------------------------------------------------
// tf32 helpers (mma.sync path — base sm_103 target OK)
// ---------------------------------------------------------------------------
__device__ __forceinline__ uint32_t f2tf32(float x) {
    uint32_t r;
    asm("cvt.rna.tf32.f32 %0, %1;" : "=r"(r) : "f"(x));
    return r;
}

__device__ __forceinline__ void mma_tf32(float* c, const uint32_t* a, const uint32_t* b) {
    asm volatile(
        "mma.sync.aligned.m16n8k8.row.col.f32.tf32.tf32.f32 "
        "{%0,%1,%2,%3}, {%4,%5,%6,%7}, {%8,%9}, {%0,%1,%2,%3};"
        : "+f"(c[0]), "+f"(c[1]), "+f"(c[2]), "+f"(c[3])
        : "r"(a[0]), "r"(a[1]), "r"(a[2]), "r"(a[3]),
          "r"(b[0]), "r"(b[1]));
}

// ---------------------------------------------------------------------------
// Weight transpose: dst[c][r] = src[r][c]
// ---------------------------------------------------------------------------
__global__ __launch_bounds__(256)
void transpose_k(const float* __restrict__ src, int dstId, int R, int C)
{
    __shared__ float t[32][33];
    float* dst = scratch(dstId);
    const int bx = blockIdx.x * 32;
    const int by = blockIdx.y * 32;
    const int tx = threadIdx.x & 31;
    const int ty = threadIdx.x >> 5;
    #pragma unroll
    for (int i = 0; i < 32; i += 8)
        t[ty + i][tx] = src[(size_t)(by + ty + i) * C + bx + tx];
    __syncthreads();
    #pragma unroll
    for (int i = 0; i < 32; i += 8)
        dst[(size_t)(bx + ty + i) * R + by + tx] = t[tx][ty + i];
}

// ---------------------------------------------------------------------------
// TF32 tensor-core GEMM: C[M,N] = A[M,K] @ Bt[N,K]^T + bias (opt ReLU)
// R4 layout (permuted, conflict-free lds.64, stride 24) + register-staged
// double buffering: ONE __syncthreads per BK=16 chunk, global loads for
// chunk k+1 issued before computing chunk k.
// ---------------------------------------------------------------------------
#define AS_STRIDE 24

__global__ __launch_bounds__(256)
void gemm_tf32(const float* __restrict__ Aext, int Aid, int Bid,
               const float* __restrict__ bias,
               float* __restrict__ Cext, int Cid,
               int M, int N, int K, int relu)
{
    __shared__ uint32_t As[2][128 * AS_STRIDE];   // 2 x 12 KB
    __shared__ uint32_t Bs[2][128 * AS_STRIDE];   // 2 x 12 KB  (total 48 KB)

    const float* A  = Aext ? Aext : scratch(Aid);
    const float* Bt = scratch(Bid);
    float*       C  = Cext ? Cext : scratch(Cid);

    const int tid   = threadIdx.x;
    const int wid   = tid >> 5;
    const int lane  = tid & 31;
    const int gid   = lane >> 2;
    const int tig   = lane & 3;
    const int warpM = (wid & 1) * 64;
    const int warpN = (wid >> 1) * 32;
    const int m0    = blockIdx.y * 128;
    const int n0    = blockIdx.x * 128;

    // loader coords (R4 scheme): each thread covers rows lr, lr+64
    const int lr    = tid >> 2;
    const int lc4   = tid & 3;
    const int wbase = (lc4 >> 1) * 8 + (lc4 & 1);

    const float* a_src0 = &A [(size_t)(m0 + lr)      * K + lc4 * 4];
    const float* a_src1 = &A [(size_t)(m0 + lr + 64) * K + lc4 * 4];
    const float* b_src0 = &Bt[(size_t)(n0 + lr)      * K + lc4 * 4];
    const float* b_src1 = &Bt[(size_t)(n0 + lr + 64) * K + lc4 * 4];

    float acc[4][4][4];
    #pragma unroll
    for (int mt = 0; mt < 4; mt++)
        #pragma unroll
        for (int nt = 0; nt < 4; nt++)
            #pragma unroll
            for (int c = 0; c < 4; c++) acc[mt][nt][c] = 0.f;

    const int nk = K >> 4;

    // prolog: load + store chunk 0 into buffer 0
    {
        float4 pa0 = *(const float4*)a_src0;
        float4 pa1 = *(const float4*)a_src1;
        float4 pb0 = *(const float4*)b_src0;
        float4 pb1 = *(const float4*)b_src1;
        uint32_t* da0 = &As[0][lr * AS_STRIDE + wbase];
        da0[0] = f2tf32(pa0.x); da0[2] = f2tf32(pa0.y);
        da0[4] = f2tf32(pa0.z); da0[6] = f2tf32(pa0.w);
        uint32_t* da1 = &As[0][(lr + 64) * AS_STRIDE + wbase];
        da1[0] = f2tf32(pa1.x); da1[2] = f2tf32(pa1.y);
        da1[4] = f2tf32(pa1.z); da1[6] = f2tf32(pa1.w);
        uint32_t* db0 = &Bs[0][lr * AS_STRIDE + wbase];
        db0[0] = f2tf32(pb0.x); db0[2] = f2tf32(pb0.y);
        db0[4] = f2tf32(pb0.z); db0[6] = f2tf32(pb0.w);
        uint32_t* db1 = &Bs[0][(lr + 64) * AS_STRIDE + wbase];
        db1[0] = f2tf32(pb1.x); db1[2] = f2tf32(pb1.y);
        db1[4] = f2tf32(pb1.z); db1[6] = f2tf32(pb1.w);
    }
    __syncthreads();

    for (int kc = 0; kc < nk; kc++) {
        const int buf = kc & 1;

        // prefetch chunk kc+1 into registers (latency hidden by MMA below)
        float4 pa0, pa1, pb0, pb1;
        const bool more = (kc + 1 < nk);
        if (more) {
            const int ko = (kc + 1) * 16;
            pa0 = *(const float4*)(a_src0 + ko);
            pa1 = *(const float4*)(a_src1 + ko);
            pb0 = *(const float4*)(b_src0 + ko);
            pb1 = *(const float4*)(b_src1 + ko);
        }

        // compute chunk kc from buffer buf
        const uint32_t* as = As[buf];
        const uint32_t* bs = Bs[buf];
        #pragma unroll
        for (int ks = 0; ks < 2; ks++) {
            uint32_t bfr[4][2];
            #pragma unroll
            for (int nt = 0; nt < 4; nt++) {
                uint2 v = *(const uint2*)&bs[(warpN + nt * 8 + gid) * AS_STRIDE + ks * 8 + 2 * tig];
                bfr[nt][0] = v.x;
                bfr[nt][1] = v.y;
            }
            #pragma unroll
            for (int mt = 0; mt < 4; mt++) {
                uint2 lo = *(const uint2*)&as[(warpM + mt * 16 +     gid) * AS_STRIDE + ks * 8 + 2 * tig];
                uint2 hi = *(const uint2*)&as[(warpM + mt * 16 + 8 + gid) * AS_STRIDE + ks * 8 + 2 * tig];
                uint32_t af[4];
                af[0] = lo.x; af[1] = hi.x; af[2] = lo.y; af[3] = hi.y;
                #pragma unroll
                for (int nt = 0; nt < 4; nt++)
                    mma_tf32(acc[mt][nt], af, bfr[nt]);
            }
        }

        // store prefetched chunk to the other buffer
        if (more) {
            const int nb = buf ^ 1;
            uint32_t* da0 = &As[nb][lr * AS_STRIDE + wbase];
            da0[0] = f2tf32(pa0.x); da0[2] = f2tf32(pa0.y);
            da0[4] = f2tf32(pa0.z); da0[6] = f2tf32(pa0.w);
            uint32_t* da1 = &As[nb][(lr + 64) * AS_STRIDE + wbase];
            da1[0] = f2tf32(pa1.x); da1[2] = f2tf32(pa1.y);
            da1[4] = f2tf32(pa1.z); da1[6] = f2tf32(pa1.w);
            uint32_t* db0 = &Bs[nb][lr * AS_STRIDE + wbase];
            db0[0] = f2tf32(pb0.x); db0[2] = f2tf32(pb0.y);
            db0[4] = f2tf32(pb0.z); db0[6] = f2tf32(pb0.w);
            uint32_t* db1 = &Bs[nb][(lr + 64) * AS_STRIDE + wbase];
            db1[0] = f2tf32(pb1.x); db1[2] = f2tf32(pb1.y);
            db1[4] = f2tf32(pb1.z); db1[6] = f2tf32(pb1.w);
            __syncthreads();
        }
    }

    #pragma unroll
    for (int nt = 0; nt < 4; nt++) {
        const int n = n0 + warpN + nt * 8 + 2 * tig;
        const float b0 = bias[n], b1 = bias[n + 1];
        #pragma unroll
        for (int mt = 0; mt < 4; mt++) {
            const int m = m0 + warpM + mt * 16 + gid;
            float2 v0 = make_float2(acc[mt][nt][0] + b0, acc[mt][nt][1] + b1);
            float2 v1 = make_float2(acc[mt][nt][2] + b0, acc[mt][nt][3] + b1);
            if (relu) {
                v0.x = fmaxf(v0.x, 0.f); v0.y = fmaxf(v0.y, 0.f);
                v1.x = fmaxf(v1.x, 0.f); v1.y = fmaxf(v1.y, 0.f);
            }
            *(float2*)&C[(size_t)m * N + n]       = v0;
            *(float2*)&C[(size_t)(m + 8) * N + n] = v1;
        }
    }
}

// ---------------------------------------------------------------------------
// Tensor-core flash attention (tf32 mma.sync) — unchanged from R4
// ---------------------------------------------------------------------------
#define KS_STRIDE 72
#define VS_STRIDE 74

__global__ __launch_bounds__(128)
void attn_mma()
{
    __shared__ uint32_t sm[64 * KS_STRIDE + 64 * VS_STRIDE];

    const int nB  = blockIdx.z;
    const int h   = blockIdx.y;
    const int q0  = blockIdx.x * 128;
    const int tid = threadIdx.x;
    const int wid = tid >> 5;
    const int lane = tid & 31;
    const int gid  = lane >> 2;
    const int tig  = lane & 3;
    const int warpM = wid * 32;
    const float qscale = 0.125f * 1.44269504f;

    #pragma unroll
    for (int t = 0; t < 16; t++) {
        const int i  = tid + t * 128;
        const int r  = i >> 4;
        const int c4 = i & 15;
        const float4 v = *(const float4*)&g_qkv[(size_t)(nB * LQ + q0 + r) * (3 * D) + h * HD + c4 * 4];
        uint32_t* dst = &sm[r * KS_STRIDE + (c4 >> 2) * 16 + ((c4 & 3) >> 1) * 8 + (c4 & 1)];
        dst[0] = f2tf32(v.x * qscale); dst[2] = f2tf32(v.y * qscale);
        dst[4] = f2tf32(v.z * qscale); dst[6] = f2tf32(v.w * qscale);
    }
    __syncthreads();

    uint32_t qf[2][8][4];
    #pragma unroll
    for (int mt = 0; mt < 2; mt++) {
        const int rlo = warpM + mt * 16 + gid;
        #pragma unroll
        for (int ks = 0; ks < 8; ks++) {
            uint2 lo = *(const uint2*)&sm[ rlo      * KS_STRIDE + (ks >> 1) * 16 + (ks & 1) * 8 + 2 * tig];
            uint2 hi = *(const uint2*)&sm[(rlo + 8) * KS_STRIDE + (ks >> 1) * 16 + (ks & 1) * 8 + 2 * tig];
            qf[mt][ks][0] = lo.x; qf[mt][ks][1] = hi.x;
            qf[mt][ks][2] = lo.y; qf[mt][ks][3] = hi.y;
        }
    }
    __syncthreads();

    uint32_t* Ks = sm;
    uint32_t* Vs = sm + 64 * KS_STRIDE;

    float oac[2][8][4];
    #pragma unroll
    for (int mt = 0; mt < 2; mt++)
        #pragma unroll
        for (int nt = 0; nt < 8; nt++)
            #pragma unroll
            for (int c = 0; c < 4; c++) oac[mt][nt][c] = 0.f;
    float mrow[2][2] = {{-1e30f, -1e30f}, {-1e30f, -1e30f}};
    float lrow[2][2] = {{0.f, 0.f}, {0.f, 0.f}};

    for (int kt = 0; kt < LQ / 64; kt++) {
        #pragma unroll
        for (int t = 0; t < 8; t++) {
            const int i  = tid + t * 128;
            const int r  = i >> 4;
            const int c4 = i & 15;
            const size_t base = (size_t)(nB * LQ + kt * 64 + r) * (3 * D) + h * HD + c4 * 4;
            const float4 v = *(const float4*)&g_qkv[base + D];
            uint32_t* dst = &Ks[r * KS_STRIDE + (c4 >> 2) * 16 + ((c4 & 3) >> 1) * 8 + (c4 & 1)];
            dst[0] = f2tf32(v.x); dst[2] = f2tf32(v.y);
            dst[4] = f2tf32(v.z); dst[6] = f2tf32(v.w);
        }
        #pragma unroll
        for (int t = 0; t < 8; t++) {
            const int i   = tid + t * 128;
            const int key = i >> 4;
            const int c4  = i & 15;
            const size_t base = (size_t)(nB * LQ + kt * 64 + key) * (3 * D) + h * HD + c4 * 4;
            const float4 v = *(const float4*)&g_qkv[base + 2 * D];
            const int kpos = (key >> 4) * 16 + ((key & 3) << 1) + ((key >> 2) & 1) + (key & 8);
            const int d0 = c4 * 4;
            Vs[(d0 + 0) * VS_STRIDE + kpos] = f2tf32(v.x);
            Vs[(d0 + 1) * VS_STRIDE + kpos] = f2tf32(v.y);
            Vs[(d0 + 2) * VS_STRIDE + kpos] = f2tf32(v.z);
            Vs[(d0 + 3) * VS_STRIDE + kpos] = f2tf32(v.w);
        }
        __syncthreads();

        float sacc[2][8][4];
        #pragma unroll
        for (int mt = 0; mt < 2; mt++)
            #pragma unroll
            for (int nt = 0; nt < 8; nt++)
                #pragma unroll
                for (int c = 0; c < 4; c++) sacc[mt][nt][c] = 0.f;

        #pragma unroll
        for (int ks = 0; ks < 8; ks++) {
            #pragma unroll
            for (int nt = 0; nt < 8; nt++) {
                uint2 bv = *(const uint2*)&Ks[(nt * 8 + gid) * KS_STRIDE + (ks >> 1) * 16 + (ks & 1) * 8 + 2 * tig];
                uint32_t bf[2] = {bv.x, bv.y};
                mma_tf32(sacc[0][nt], qf[0][ks], bf);
                mma_tf32(sacc[1][nt], qf[1][ks], bf);
            }
        }

        #pragma unroll
        for (int mt = 0; mt < 2; mt++) {
            float mx0 = -1e30f, mx1 = -1e30f;
            #pragma unroll
            for (int nt = 0; nt < 8; nt++) {
                mx0 = fmaxf(mx0, fmaxf(sacc[mt][nt][0], sacc[mt][nt][1]));
                mx1 = fmaxf(mx1, fmaxf(sacc[mt][nt][2], sacc[mt][nt][3]));
            }
            mx0 = fmaxf(mx0, __shfl_xor_sync(0xFFFFFFFFu, mx0, 1));
            mx0 = fmaxf(mx0, __shfl_xor_sync(0xFFFFFFFFu, mx0, 2));
            mx1 = fmaxf(mx1, __shfl_xor_sync(0xFFFFFFFFu, mx1, 1));
            mx1 = fmaxf(mx1, __shfl_xor_sync(0xFFFFFFFFu, mx1, 2));

            const float mn0 = fmaxf(mrow[mt][0], mx0);
            const float mn1 = fmaxf(mrow[mt][1], mx1);
            const float cr0 = exp2f(mrow[mt][0] - mn0);
            const float cr1 = exp2f(mrow[mt][1] - mn1);
            mrow[mt][0] = mn0;
            mrow[mt][1] = mn1;

            float ls0 = 0.f, ls1 = 0.f;
            #pragma unroll
            for (int nt = 0; nt < 8; nt++) {
                sacc[mt][nt][0] = exp2f(sacc[mt][nt][0] - mn0);
                sacc[mt][nt][1] = exp2f(sacc[mt][nt][1] - mn0);
                sacc[mt][nt][2] = exp2f(sacc[mt][nt][2] - mn1);
                sacc[mt][nt][3] = exp2f(sacc[mt][nt][3] - mn1);
                ls0 += sacc[mt][nt][0] + sacc[mt][nt][1];
                ls1 += sacc[mt][nt][2] + sacc[mt][nt][3];
            }
            ls0 += __shfl_xor_sync(0xFFFFFFFFu, ls0, 1);
            ls0 += __shfl_xor_sync(0xFFFFFFFFu, ls0, 2);
            ls1 += __shfl_xor_sync(0xFFFFFFFFu, ls1, 1);
            ls1 += __shfl_xor_sync(0xFFFFFFFFu, ls1, 2);
            lrow[mt][0] = lrow[mt][0] * cr0 + ls0;
            lrow[mt][1] = lrow[mt][1] * cr1 + ls1;

            #pragma unroll
            for (int nt = 0; nt < 8; nt++) {
                oac[mt][nt][0] *= cr0; oac[mt][nt][1] *= cr0;
                oac[mt][nt][2] *= cr1; oac[mt][nt][3] *= cr1;
            }
        }

        const int s1 = (lane & ~3) | (tig >> 1);
        const int s2 = s1 + 2;
        const bool odd = (tig & 1) != 0;
        #pragma unroll
        for (int kk = 0; kk < 8; kk++) {
            uint32_t pa[2][4];
            #pragma unroll
            for (int mt = 0; mt < 2; mt++) {
                const float c0 = sacc[mt][kk][0], c1 = sacc[mt][kk][1];
                const float c2 = sacc[mt][kk][2], c3 = sacc[mt][kk][3];
                const float x0 = __shfl_sync(0xFFFFFFFFu, c0, s1);
                const float x1 = __shfl_sync(0xFFFFFFFFu, c1, s1);
                const float x2 = __shfl_sync(0xFFFFFFFFu, c2, s1);
                const float x3 = __shfl_sync(0xFFFFFFFFu, c3, s1);
                const float y0 = __shfl_sync(0xFFFFFFFFu, c0, s2);
                const float y1 = __shfl_sync(0xFFFFFFFFu, c1, s2);
                const float y2 = __shfl_sync(0xFFFFFFFFu, c2, s2);
                const float y3 = __shfl_sync(0xFFFFFFFFu, c3, s2);
                pa[mt][0] = f2tf32(odd ? x1 : x0);
                pa[mt][1] = f2tf32(odd ? x3 : x2);
                pa[mt][2] = f2tf32(odd ? y1 : y0);
                pa[mt][3] = f2tf32(odd ? y3 : y2);
            }
            #pragma unroll
            for (int ntd = 0; ntd < 8; ntd++) {
                uint2 bv = *(const uint2*)&Vs[(ntd * 8 + gid) * VS_STRIDE + (kk >> 1) * 16 + (kk & 1) * 8 + 2 * tig];
                uint32_t bf[2] = {bv.x, bv.y};
                mma_tf32(oac[0][ntd], pa[0], bf);
                mma_tf32(oac[1][ntd], pa[1], bf);
            }
        }
        __syncthreads();
    }

    #pragma unroll
    for (int mt = 0; mt < 2; mt++) {
        const float inv0 = 1.f / lrow[mt][0];
        const float inv1 = 1.f / lrow[mt][1];
        const int grow = nB * LQ + q0 + warpM + mt * 16 + gid;
        #pragma unroll
        for (int ntd = 0; ntd < 8; ntd++) {
            const int col = h * HD + ntd * 8 + 2 * tig;
            *(float2*)&g_attn[(size_t)grow * D + col] =
                make_float2(oac[mt][ntd][0] * inv0, oac[mt][ntd][1] * inv0);
            *(float2*)&g_attn[(size_t)(grow + 8) * D + col] =
                make_float2(oac[mt][ntd][2] * inv1, oac[mt][ntd][3] * inv1);
        }
    }
}

// ---------------------------------------------------------------------------
// Residual add + LayerNorm
// ---------------------------------------------------------------------------
__global__ __launch_bounds__(256)
void add_ln_kernel(const float* __restrict__ aext, int aid,
                   const float* __restrict__ bext, int bid,
                   const float* __restrict__ gamma,
                   const float* __restrict__ beta,
                   float* __restrict__ outext, int outid)
{
    const float* a = aext ? aext : scratch(aid);
    const float* b = bext ? bext : scratch(bid);
    float*       o = outext ? outext : scratch(outid);

    const int row = blockIdx.x;
    const int tid = threadIdx.x;
    const size_t base = (size_t)row * D;

    float v[4];
    float s = 0.f, s2 = 0.f;
    #pragma unroll
    for (int i = 0; i < 4; i++) {
        int col = tid + i * 256;
        float x = a[base + col] + b[base + col];
        v[i] = x;
        s  += x;
        s2 += x * x;
    }
    #pragma unroll
    for (int off = 16; off; off >>= 1) {
        s  += __shfl_xor_sync(0xFFFFFFFFu, s,  off);
        s2 += __shfl_xor_sync(0xFFFFFFFFu, s2, off);
    }
    __shared__ float rs[8], rs2[8];
    const int warp = tid >> 5, lane = tid & 31;
    if (lane == 0) { rs[warp] = s; rs2[warp] = s2; }
    __syncthreads();
    float ts = 0.f, ts2 = 0.f;
    #pragma unroll
    for (int w = 0; w < 8; w++) { ts += rs[w]; ts2 += rs2[w]; }

    const float mu  = ts * (1.f / D);
    const float var = ts2 * (1.f / D) - mu * mu;
    const float inv = rsqrtf(var + EPS);

    #pragma unroll
    for (int i = 0; i < 4; i++) {
        int col = tid + i * 256;
        o[base + col] = (v[i] - mu) * inv * gamma[col] + beta[col];
    }
}

// ---------------------------------------------------------------------------
// Launch
// ---------------------------------------------------------------------------
extern "C" void kernel_launch(void* const* d_in, const int* in_sizes, int n_in,
                              void* d_out, int out_size)
{
    const float* x     = (const float*)d_in[0];
    const float* w_qkv = (const float*)d_in[1];
    const float* b_qkv = (const float*)d_in[2];
    const float* w_o   = (const float*)d_in[3];
    const float* b_o   = (const float*)d_in[4];
    const float* g1    = (const float*)d_in[5];
    const float* be1   = (const float*)d_in[6];
    const float* w1    = (const float*)d_in[7];
    const float* b1    = (const float*)d_in[8];
    const float* w2    = (const float*)d_in[9];
    const float* b2    = (const float*)d_in[10];
    const float* g2    = (const float*)d_in[11];
    const float* be2   = (const float*)d_in[12];
    float* out = (float*)d_out;

    // Transpose weights -> [N,K] K-major operands
    transpose_k<<<dim3(3 * D / 32, D / 32), 256>>>(w_qkv, 6, D, 3 * D);
    transpose_k<<<dim3(D / 32,     D / 32), 256>>>(w_o,   7, D, D);
    transpose_k<<<dim3(FF / 32,    D / 32), 256>>>(w1,    8, D, FF);
    transpose_k<<<dim3(D / 32,    FF / 32), 256>>>(w2,    9, FF, D);

    // 1. QKV
    gemm_tf32<<<dim3(3 * D / 128, MROWS / 128), 256>>>(
        x, -1, 6, b_qkv, nullptr, 0, MROWS, 3 * D, D, 0);

    // 2. attention (tensor-core flash)
    attn_mma<<<dim3(LQ / 128, H_, NB), 128>>>();

    // 3. proj
    gemm_tf32<<<dim3(D / 128, MROWS / 128), 256>>>(
        nullptr, 1, 7, b_o, nullptr, 2, MROWS, D, D, 0);

    // 4. h = LN(proj + x)
    add_ln_kernel<<<MROWS, 256>>>(nullptr, 2, x, -1, g1, be1, nullptr, 3);

    // 5. FF1 (+ReLU)
    gemm_tf32<<<dim3(FF / 128, MROWS / 128), 256>>>(
        nullptr, 3, 8, b1, nullptr, 4, MROWS, FF, D, 1);

    // 6. FF2
    gemm_tf32<<<dim3(D / 128, MROWS / 128), 256>>>(
        nullptr, 4, 9, b2, nullptr, 5, MROWS, D, FF, 0);

    // 7. out = LN(h + ff2)
    add_ln_kernel<<<MROWS, 256>>>(nullptr, 3, nullptr, 5, g2, be2, out, -1);
}